// round 15
// baseline (speedup 1.0000x reference)
#include <cuda_runtime.h>
#include <cuda_bf16.h>
#include <math.h>
#include <stdint.h>

#define Bsz 2
#define Slen 2048
#define Dm 512
#define Hh 8
#define Aa 64
#define Ll 2
#define Tt 256
#define Mrows (Bsz*Slen)
#define LN_EPS 1e-5f

__device__ float g_x[Mrows*Dm];
__device__ float g_tmp[Mrows*Dm];
__device__ __nv_bfloat16 g_xh[Mrows*Dm],  g_xl[Mrows*Dm];
__device__ __nv_bfloat16 g_qh[Bsz*Hh*Slen*Aa], g_ql[Bsz*Hh*Slen*Aa];
__device__ __nv_bfloat16 g_kh[Bsz*Hh*Slen*Aa], g_kl[Bsz*Hh*Slen*Aa];
__device__ __nv_bfloat16 g_vh[Bsz*Hh*Slen*Aa], g_vl[Bsz*Hh*Slen*Aa];
__device__ __nv_bfloat16 g_hh[Mrows*Dm],  g_hl[Mrows*Dm];
__device__ __nv_bfloat16 g_1h[Mrows*Dm],  g_1l[Mrows*Dm];
__device__ __nv_bfloat16 g_wqkv_h[Ll*1536*512], g_wqkv_l[Ll*1536*512];
__device__ __nv_bfloat16 g_wo_h[Ll*512*512],    g_wo_l[Ll*512*512];
__device__ __nv_bfloat16 g_w1_h[Ll*512*512],    g_w1_l[Ll*512*512];
__device__ __nv_bfloat16 g_w2_h[Ll*512*512],    g_w2_l[Ll*512*512];
__device__ __nv_bfloat16 g_wp_h[Tt*512],        g_wp_l[Tt*512];

__device__ __forceinline__ uint32_t smem_u32(const void* p) {
    uint32_t a;
    asm("{ .reg .u64 t; cvta.to.shared.u64 t, %1; cvt.u32.u64 %0, t; }" : "=r"(a) : "l"(p));
    return a;
}
__device__ __forceinline__ uint32_t pack2(float x, float y) {
    return (uint32_t)__bfloat16_as_ushort(__float2bfloat16(x)) |
           ((uint32_t)__bfloat16_as_ushort(__float2bfloat16(y)) << 16);
}
__device__ __forceinline__ void ldsm4(uint32_t* r, uint32_t addr) {
    asm volatile("ldmatrix.sync.aligned.m8n8.x4.shared.b16 {%0,%1,%2,%3}, [%4];"
        : "=r"(r[0]), "=r"(r[1]), "=r"(r[2]), "=r"(r[3]) : "r"(addr));
}
__device__ __forceinline__ void ldsm4t(uint32_t* r, uint32_t addr) {
    asm volatile("ldmatrix.sync.aligned.m8n8.x4.trans.shared.b16 {%0,%1,%2,%3}, [%4];"
        : "=r"(r[0]), "=r"(r[1]), "=r"(r[2]), "=r"(r[3]) : "r"(addr));
}
__device__ __forceinline__ void mma16816(float* d, const uint32_t* a, const uint32_t* b) {
    asm volatile("mma.sync.aligned.m16n8k16.row.col.f32.bf16.bf16.f32 "
        "{%0,%1,%2,%3}, {%4,%5,%6,%7}, {%8,%9}, {%0,%1,%2,%3};"
        : "+f"(d[0]), "+f"(d[1]), "+f"(d[2]), "+f"(d[3])
        : "r"(a[0]), "r"(a[1]), "r"(a[2]), "r"(a[3]), "r"(b[0]), "r"(b[1]));
}
#define CP16(sa, gp) asm volatile("cp.async.cg.shared.global [%0], [%1], 16;" :: "r"(sa), "l"(gp))
#define CP_COMMIT()  asm volatile("cp.async.commit_group;" ::: "memory")
#define CP_WAIT0()   asm volatile("cp.async.wait_group 0;" ::: "memory")
#define CP_WAIT1()   asm volatile("cp.async.wait_group 1;" ::: "memory")

#define RSB 144
#define GSTG (4*128*RSB)    // 73728
#define FSTG (4*64*RSB)     // 36864

// ---- input convert ----
__global__ __launch_bounds__(256)
void conv_x(const float* __restrict__ xin, float* __restrict__ xout,
            __nv_bfloat16* __restrict__ xh, __nv_bfloat16* __restrict__ xl)
{
    int i = blockIdx.x * 256 + threadIdx.x;
    float2 v = *reinterpret_cast<const float2*>(xin + 2*i);
    *reinterpret_cast<float2*>(xout + 2*i) = v;
    float hx = __bfloat162float(__float2bfloat16(v.x));
    float hy = __bfloat162float(__float2bfloat16(v.y));
    *reinterpret_cast<uint32_t*>(xh + 2*i) = pack2(v.x, v.y);
    *reinterpret_cast<uint32_t*>(xl + 2*i) = pack2(v.x - hx, v.y - hy);
}

// ---- weight prep ----
__global__ void prep_all(const float* __restrict__ Wo, const float* __restrict__ W1,
                         const float* __restrict__ W2, const float* __restrict__ Wp,
                         __nv_bfloat16* __restrict__ woh, __nv_bfloat16* __restrict__ wol,
                         __nv_bfloat16* __restrict__ w1h, __nv_bfloat16* __restrict__ w1l,
                         __nv_bfloat16* __restrict__ w2h, __nv_bfloat16* __restrict__ w2l,
                         __nv_bfloat16* __restrict__ wph, __nv_bfloat16* __restrict__ wpl)
{
    int z = blockIdx.z;
    const float* W; __nv_bfloat16 *hi, *lo; int N;
    if (z < 2)      { W = Wo + (size_t)z*512*512; hi = woh + (size_t)z*512*512; lo = wol + (size_t)z*512*512; N = 512; }
    else if (z < 4) { int l = z-2; W = W1 + (size_t)l*512*512; hi = w1h + (size_t)l*512*512; lo = w1l + (size_t)l*512*512; N = 512; }
    else if (z < 6) { int l = z-4; W = W2 + (size_t)l*512*512; hi = w2h + (size_t)l*512*512; lo = w2l + (size_t)l*512*512; N = 512; }
    else            { W = Wp; hi = wph; lo = wpl; N = 256; }
    int k0 = blockIdx.x * 32, n0 = blockIdx.y * 32;
    if (n0 >= N) return;
    __shared__ float t[32][33];
    for (int i = threadIdx.y; i < 32; i += 8)
        t[i][threadIdx.x] = W[(size_t)(k0 + i) * N + n0 + threadIdx.x];
    __syncthreads();
    for (int i = threadIdx.y; i < 32; i += 8) {
        float v = t[threadIdx.x][i];
        __nv_bfloat16 h = __float2bfloat16(v);
        hi[(size_t)(n0 + i) * 512 + k0 + threadIdx.x] = h;
        lo[(size_t)(n0 + i) * 512 + k0 + threadIdx.x] = __float2bfloat16(v - __bfloat162float(h));
    }
}
__global__ void prep_qkv_w(const float* __restrict__ Wq, const float* __restrict__ Wk,
                           const float* __restrict__ Wv,
                           __nv_bfloat16* __restrict__ hi, __nv_bfloat16* __restrict__ lo)
{
    int bz = blockIdx.z;
    int l = bz / 24, rem = bz % 24, zz = rem / 8, h = rem % 8;
    const float* W = (zz == 0 ? Wq : zz == 1 ? Wk : Wv) + ((size_t)(l * Hh + h)) * Dm * Aa;
    size_t nb = (size_t)l * 1536 + zz * 512 + h * 64;
    __shared__ float t[32][33];
    int d0 = blockIdx.x * 32, a0 = blockIdx.y * 32;
    for (int i = threadIdx.y; i < 32; i += 8)
        t[i][threadIdx.x] = W[(size_t)(d0 + i) * Aa + a0 + threadIdx.x];
    __syncthreads();
    for (int i = threadIdx.y; i < 32; i += 8) {
        float v = t[threadIdx.x][i];
        __nv_bfloat16 hv = __float2bfloat16(v);
        hi[(nb + a0 + i) * 512 + d0 + threadIdx.x] = hv;
        lo[(nb + a0 + i) * 512 + d0 + threadIdx.x] = __float2bfloat16(v - __bfloat162float(hv));
    }
}

// ---------------------------------------------------------------------------
// HMMA GEMM (R8 tiles): 512 thr, CTA 128x128, 3 stages, prefetch-dist-2,
// ONE __syncthreads per chunk.
// ---------------------------------------------------------------------------
__global__ __launch_bounds__(512)
void gemm_mma(const __nv_bfloat16* __restrict__ Ah_g, const __nv_bfloat16* __restrict__ Al_g,
              const __nv_bfloat16* __restrict__ Bh_g, const __nv_bfloat16* __restrict__ Bl_g,
              const float* __restrict__ bias0, const float* __restrict__ bias1,
              const float* __restrict__ bias2,
              float* __restrict__ C0,
              __nv_bfloat16* __restrict__ H0, __nv_bfloat16* __restrict__ L0,
              __nv_bfloat16* __restrict__ H1, __nv_bfloat16* __restrict__ L1,
              __nv_bfloat16* __restrict__ H2, __nv_bfloat16* __restrict__ L2,
              int ldC, int relu, int mode)
{
    extern __shared__ char smem[];
    const uint32_t uS = smem_u32(smem);

    const int tid = threadIdx.x;
    const int wid = tid >> 5, lid = tid & 31;
    const int wm = wid >> 2, wn = wid & 3;
    const int g = lid >> 2, tg = lid & 3;
    const int m0 = blockIdx.y * 128, n0 = blockIdx.x * 128;

    float acc[2][4][4];
    #pragma unroll
    for (int i = 0; i < 2; i++)
        #pragma unroll
        for (int j = 0; j < 4; j++)
            #pragma unroll
            for (int e = 0; e < 4; e++) acc[i][j][e] = 0.0f;

    const int a_row = (lid & 7) + ((lid >> 3) & 1) * 8;
    const int a_colb = ((lid >> 4) & 1) * 16;
    const int b_row = (lid & 7) + ((lid >> 4) & 1) * 8;
    const int b_colb = ((lid >> 3) & 1) * 16;
    const int ld_row = tid >> 3, ld_kq = tid & 7;

    auto load_chunk = [&](int c, int st) {
        const uint32_t sb = uS + (uint32_t)st * GSTG;
        const int kt = c * 64;
        #pragma unroll
        for (int it = 0; it < 2; it++) {
            int row = ld_row + it * 64;
            const size_t ba = (size_t)(m0 + row) * 512 + kt + ld_kq * 8;
            uint32_t so = (uint32_t)(row * RSB + ld_kq * 16);
            CP16(sb + so,            Ah_g + ba);
            CP16(sb + 128*RSB + so,  Al_g + ba);
            const size_t bb = (size_t)(n0 + row) * 512 + kt + ld_kq * 8;
            CP16(sb + 2*128*RSB + so, Bh_g + bb);
            CP16(sb + 3*128*RSB + so, Bl_g + bb);
        }
    };

    load_chunk(0, 0); CP_COMMIT();
    load_chunk(1, 1); CP_COMMIT();

    for (int c = 0; c < 8; c++) {
        if (c == 7) CP_WAIT0(); else CP_WAIT1();
        __syncthreads();
        if (c + 2 < 8) { load_chunk(c + 2, (c + 2) % 3); CP_COMMIT(); }

        const uint32_t sb = uS + (uint32_t)(c % 3) * GSTG;
        const uint32_t uAh = sb, uAl = sb + 128*RSB;
        const uint32_t uBh = sb + 2*128*RSB, uBl = sb + 3*128*RSB;

        #pragma unroll
        for (int ks = 0; ks < 4; ks++) {
            const int kb = ks * 32;
            uint32_t bh[8], bl[8];
            #pragma unroll
            for (int jt = 0; jt < 2; jt++) {
                uint32_t addr = (wn * 32 + jt * 16 + b_row) * RSB + kb + b_colb;
                ldsm4(bh + jt * 4, uBh + addr);
                ldsm4(bl + jt * 4, uBl + addr);
            }
            #pragma unroll
            for (int i = 0; i < 2; i++) {
                uint32_t ah[4], al[4];
                uint32_t addr = (wm * 32 + i * 16 + a_row) * RSB + kb + a_colb;
                ldsm4(ah, uAh + addr);
                ldsm4(al, uAl + addr);
                #pragma unroll
                for (int j = 0; j < 4; j++) {
                    mma16816(acc[i][j], ah, bh + j * 2);
                    mma16816(acc[i][j], ah, bl + j * 2);
                    mma16816(acc[i][j], al, bh + j * 2);
                }
            }
        }
    }

    const int mb = m0 + wm * 32;
    const int nb = n0 + wn * 32;
    #pragma unroll
    for (int i = 0; i < 2; i++) {
        #pragma unroll
        for (int rhalf = 0; rhalf < 2; rhalf++) {
            const int m = mb + i * 16 + g + rhalf * 8;
            const int b_ = m >> 11, s = m & 2047;
            #pragma unroll
            for (int j = 0; j < 4; j++) {
                const int ncol = nb + j * 8 + 2 * tg;
                float vx = acc[i][j][rhalf * 2 + 0];
                float vy = acc[i][j][rhalf * 2 + 1];
                if (mode == 0) {
                    vx += bias0[ncol]; vy += bias0[ncol + 1];
                    if (relu) { vx = fmaxf(vx, 0.f); vy = fmaxf(vy, 0.f); }
                    float2 o = {vx, vy};
                    *reinterpret_cast<float2*>(C0 + (size_t)m * ldC + ncol) = o;
                } else if (mode == 1) {
                    const int z = ncol >> 9, rr = ncol & 511;
                    const int h = rr >> 6, a = rr & 63;
                    const float* bias = (z == 0) ? bias0 : (z == 1) ? bias1 : bias2;
                    vx += bias[rr]; vy += bias[rr + 1];
                    if (z == 0) { vx *= 0.125f; vy *= 0.125f; }
                    __nv_bfloat16* Hp = (z == 0) ? H0 : (z == 1) ? H1 : H2;
                    __nv_bfloat16* Lp = (z == 0) ? L0 : (z == 1) ? L1 : L2;
                    const size_t off = (((size_t)(b_ * Hh + h) * Slen + s) * 64) + a;
                    float hx = __bfloat162float(__float2bfloat16(vx));
                    float hy = __bfloat162float(__float2bfloat16(vy));
                    *reinterpret_cast<uint32_t*>(Hp + off) = pack2(vx, vy);
                    *reinterpret_cast<uint32_t*>(Lp + off) = pack2(vx - hx, vy - hy);
                } else {
                    vx += bias0[ncol]; vy += bias0[ncol + 1];
                    vx = fmaxf(vx, 0.f); vy = fmaxf(vy, 0.f);
                    const size_t off = (size_t)m * ldC + ncol;
                    float hx = __bfloat162float(__float2bfloat16(vx));
                    float hy = __bfloat162float(__float2bfloat16(vy));
                    *reinterpret_cast<uint32_t*>(H0 + off) = pack2(vx, vy);
                    *reinterpret_cast<uint32_t*>(L0 + off) = pack2(vx - hx, vy - hy);
                }
            }
        }
    }
}

// ---------------------------------------------------------------------------
// Flash attention (R8 tiles): 512 thr, 256 q/CTA, 3-stage KV, prefetch-dist-2,
// ONE __syncthreads per chunk. smem = 73728 + 3*36864 = 184320.
// ---------------------------------------------------------------------------
__global__ __launch_bounds__(512)
void flash_mma(const __nv_bfloat16* __restrict__ Qh, const __nv_bfloat16* __restrict__ Ql,
               const __nv_bfloat16* __restrict__ Kh, const __nv_bfloat16* __restrict__ Kl,
               const __nv_bfloat16* __restrict__ Vh, const __nv_bfloat16* __restrict__ Vl,
               __nv_bfloat16* __restrict__ Oh, __nv_bfloat16* __restrict__ Ol)
{
    extern __shared__ char smem[];
    const uint32_t uQh = smem_u32(smem);
    const uint32_t uQl = uQh + 256*RSB;
    const uint32_t uKV = uQh + 2*256*RSB;

    const int s0 = blockIdx.x * 256, h = blockIdx.y, b = blockIdx.z;
    const size_t bh_off = ((size_t)(b*Hh + h) * Slen) * Aa;
    const __nv_bfloat16* Qhb = Qh + bh_off; const __nv_bfloat16* Qlb = Ql + bh_off;
    const __nv_bfloat16* Khb = Kh + bh_off; const __nv_bfloat16* Klb = Kl + bh_off;
    const __nv_bfloat16* Vhb = Vh + bh_off; const __nv_bfloat16* Vlb = Vl + bh_off;

    const int tid = threadIdx.x;
    const int wid = tid >> 5, lid = tid & 31;
    const int ld_row = tid >> 3, ld_kq = tid & 7;

    // Q tile (joins cp.async group 0)
    #pragma unroll
    for (int it = 0; it < 4; it++) {
        int row = ld_row + it * 64;
        const size_t base = (size_t)(s0 + row) * Aa + ld_kq * 8;
        uint32_t so = (uint32_t)(row * RSB + ld_kq * 16);
        CP16(uQh + so, Qhb + base);
        CP16(uQl + so, Qlb + base);
    }

    auto loadKV = [&](int ci, int st) {
        const uint32_t sb = uKV + (uint32_t)st * FSTG;
        const int c0 = ci * 64;
        const size_t base = (size_t)(c0 + ld_row) * Aa + ld_kq * 8;
        uint32_t so = (uint32_t)(ld_row * RSB + ld_kq * 16);
        CP16(sb + so,            Khb + base);
        CP16(sb + 64*RSB + so,   Klb + base);
        CP16(sb + 2*64*RSB + so, Vhb + base);
        CP16(sb + 3*64*RSB + so, Vlb + base);
    };

    loadKV(0, 0); CP_COMMIT();
    loadKV(1, 1); CP_COMMIT();

    const int a_row = (lid & 7) + ((lid >> 3) & 1) * 8;
    const int a_colb = ((lid >> 4) & 1) * 16;
    const int b_row = (lid & 7) + ((lid >> 4) & 1) * 8;
    const int b_colb = ((lid >> 3) & 1) * 16;
    const int v_row = (lid & 7) + ((lid >> 3) & 1) * 8;
    const int v_colb = ((lid >> 4) & 1) * 16;

    float m0 = -INFINITY, m1 = -INFINITY, l0 = 0.0f, l1 = 0.0f;
    float accO[8][4];
    #pragma unroll
    for (int j = 0; j < 8; j++)
        #pragma unroll
        for (int e = 0; e < 4; e++) accO[j][e] = 0.0f;

    const int NC = Slen / 64;
    for (int ci = 0; ci < NC; ci++) {
        if (ci == NC - 1) CP_WAIT0(); else CP_WAIT1();
        __syncthreads();
        if (ci + 2 < NC) { loadKV(ci + 2, (ci + 2) % 3); CP_COMMIT(); }

        const uint32_t sb = uKV + (uint32_t)(ci % 3) * FSTG;
        const uint32_t uKh = sb, uKl = sb + 64*RSB;
        const uint32_t uVh = sb + 2*64*RSB, uVl = sb + 3*64*RSB;

        float accS[8][4];
        #pragma unroll
        for (int j = 0; j < 8; j++)
            #pragma unroll
            for (int e = 0; e < 4; e++) accS[j][e] = 0.0f;

        #pragma unroll
        for (int ks = 0; ks < 4; ks++) {
            const int kb = ks * 32;
            uint32_t qh[4], ql[4];
            ldsm4(qh, uQh + (wid * 16 + a_row) * RSB + kb + a_colb);
            ldsm4(ql, uQl + (wid * 16 + a_row) * RSB + kb + a_colb);
            uint32_t kh[16], kl[16];
            #pragma unroll
            for (int jt = 0; jt < 4; jt++) {
                uint32_t addr = (jt * 16 + b_row) * RSB + kb + b_colb;
                ldsm4(kh + jt * 4, uKh + addr);
                ldsm4(kl + jt * 4, uKl + addr);
            }
            #pragma unroll
            for (int j = 0; j < 8; j++) {
                const int base = (j >> 1) * 4 + (j & 1) * 2;
                mma16816(accS[j], qh, kh + base);
                mma16816(accS[j], qh, kl + base);
                mma16816(accS[j], ql, kh + base);
            }
        }

        float mx0 = -INFINITY, mx1 = -INFINITY;
        #pragma unroll
        for (int j = 0; j < 8; j++) {
            mx0 = fmaxf(mx0, fmaxf(accS[j][0], accS[j][1]));
            mx1 = fmaxf(mx1, fmaxf(accS[j][2], accS[j][3]));
        }
        mx0 = fmaxf(mx0, __shfl_xor_sync(0xffffffffu, mx0, 1));
        mx0 = fmaxf(mx0, __shfl_xor_sync(0xffffffffu, mx0, 2));
        mx1 = fmaxf(mx1, __shfl_xor_sync(0xffffffffu, mx1, 1));
        mx1 = fmaxf(mx1, __shfl_xor_sync(0xffffffffu, mx1, 2));
        const float mn0 = fmaxf(m0, mx0), mn1 = fmaxf(m1, mx1);
        const float fac0 = __expf(m0 - mn0), fac1 = __expf(m1 - mn1);
        float sum0 = 0.0f, sum1 = 0.0f;
        #pragma unroll
        for (int j = 0; j < 8; j++) {
            accS[j][0] = __expf(accS[j][0] - mn0);
            accS[j][1] = __expf(accS[j][1] - mn0);
            accS[j][2] = __expf(accS[j][2] - mn1);
            accS[j][3] = __expf(accS[j][3] - mn1);
            sum0 += accS[j][0] + accS[j][1];
            sum1 += accS[j][2] + accS[j][3];
        }
        sum0 += __shfl_xor_sync(0xffffffffu, sum0, 1);
        sum0 += __shfl_xor_sync(0xffffffffu, sum0, 2);
        sum1 += __shfl_xor_sync(0xffffffffu, sum1, 1);
        sum1 += __shfl_xor_sync(0xffffffffu, sum1, 2);
        l0 = l0 * fac0 + sum0;  m0 = mn0;
        l1 = l1 * fac1 + sum1;  m1 = mn1;
        #pragma unroll
        for (int j = 0; j < 8; j++) {
            accO[j][0] *= fac0; accO[j][1] *= fac0;
            accO[j][2] *= fac1; accO[j][3] *= fac1;
        }

        #pragma unroll
        for (int ks = 0; ks < 4; ks++) {
            uint32_t ph[4], pl[4];
            {
                const float* p0 = accS[2*ks];
                const float* p1 = accS[2*ks + 1];
                float h00 = __bfloat162float(__float2bfloat16(p0[0]));
                float h01 = __bfloat162float(__float2bfloat16(p0[1]));
                float h02 = __bfloat162float(__float2bfloat16(p0[2]));
                float h03 = __bfloat162float(__float2bfloat16(p0[3]));
                float h10 = __bfloat162float(__float2bfloat16(p1[0]));
                float h11 = __bfloat162float(__float2bfloat16(p1[1]));
                float h12 = __bfloat162float(__float2bfloat16(p1[2]));
                float h13 = __bfloat162float(__float2bfloat16(p1[3]));
                ph[0] = pack2(p0[0], p0[1]);  ph[1] = pack2(p0[2], p0[3]);
                ph[2] = pack2(p1[0], p1[1]);  ph[3] = pack2(p1[2], p1[3]);
                pl[0] = pack2(p0[0]-h00, p0[1]-h01);
                pl[1] = pack2(p0[2]-h02, p0[3]-h03);
                pl[2] = pack2(p1[0]-h10, p1[1]-h11);
                pl[3] = pack2(p1[2]-h12, p1[3]-h13);
            }
            uint32_t vh[16], vl[16];
            #pragma unroll
            for (int jt = 0; jt < 4; jt++) {
                uint32_t addr = (ks * 16 + v_row) * RSB + jt * 32 + v_colb;
                ldsm4t(vh + jt * 4, uVh + addr);
                ldsm4t(vl + jt * 4, uVl + addr);
            }
            #pragma unroll
            for (int j = 0; j < 8; j++) {
                const int base = (j >> 1) * 4 + (j & 1) * 2;
                mma16816(accO[j], ph, vh + base);
                mma16816(accO[j], ph, vl + base);
                mma16816(accO[j], pl, vh + base);
            }
        }
    }

    const float inv0 = 1.0f / l0, inv1 = 1.0f / l1;
    const int r0 = s0 + wid * 16 + (lid >> 2);
    const int r1 = r0 + 8;
    #pragma unroll
    for (int j = 0; j < 8; j++) {
        const int a = j * 8 + 2 * (lid & 3);
        float x0 = accO[j][0] * inv0, y0 = accO[j][1] * inv0;
        float x1 = accO[j][2] * inv1, y1 = accO[j][3] * inv1;
        float hx0 = __bfloat162float(__float2bfloat16(x0));
        float hy0 = __bfloat162float(__float2bfloat16(y0));
        float hx1 = __bfloat162float(__float2bfloat16(x1));
        float hy1 = __bfloat162float(__float2bfloat16(y1));
        const size_t o0 = (((size_t)b * Slen + r0) * Hh + h) * Aa + a;
        const size_t o1 = (((size_t)b * Slen + r1) * Hh + h) * Aa + a;
        *reinterpret_cast<uint32_t*>(Oh + o0) = pack2(x0, y0);
        *reinterpret_cast<uint32_t*>(Ol + o0) = pack2(x0 - hx0, y0 - hy0);
        *reinterpret_cast<uint32_t*>(Oh + o1) = pack2(x1, y1);
        *reinterpret_cast<uint32_t*>(Ol + o1) = pack2(x1 - hx1, y1 - hy1);
    }
}

// ---------------- fused add + LayerNorm ----------------
__global__ __launch_bounds__(256)
void addln_kernel(float* __restrict__ x, const float* __restrict__ t,
                  const float* __restrict__ g, const float* __restrict__ beta,
                  __nv_bfloat16* __restrict__ xh, __nv_bfloat16* __restrict__ xl)
{
    const int r = blockIdx.x, tid = threadIdx.x;
    const int c = 2 * tid;
    float2 xv = *reinterpret_cast<const float2*>(x + (size_t)r*Dm + c);
    float2 tv = *reinterpret_cast<const float2*>(t + (size_t)r*Dm + c);
    float v0 = xv.x + tv.x, v1 = xv.y + tv.y;
    float s = v0 + v1, ss = v0*v0 + v1*v1;
    #pragma unroll
    for (int off = 16; off >= 1; off >>= 1) {
        s  += __shfl_xor_sync(0xffffffffu, s,  off);
        ss += __shfl_xor_sync(0xffffffffu, ss, off);
    }
    __shared__ float red_s[8], red_ss[8], sm_mean, sm_rstd;
    int wid = tid >> 5, lane = tid & 31;
    if (lane == 0) { red_s[wid] = s; red_ss[wid] = ss; }
    __syncthreads();
    if (tid == 0) {
        float S = 0.f, SS = 0.f;
        #pragma unroll
        for (int w = 0; w < 8; w++) { S += red_s[w]; SS += red_ss[w]; }
        float mean = S * (1.0f / Dm);
        sm_mean = mean;
        sm_rstd = rsqrtf(SS * (1.0f / Dm) - mean * mean + LN_EPS);
    }
    __syncthreads();
    float mean = sm_mean, rstd = sm_rstd;
    float2 gv = *reinterpret_cast<const float2*>(g + c);
    float2 bv = *reinterpret_cast<const float2*>(beta + c);
    float o0 = (v0 - mean) * rstd * gv.x + bv.x;
    float o1 = (v1 - mean) * rstd * gv.y + bv.y;
    float2 ov = {o0, o1};
    *reinterpret_cast<float2*>(x + (size_t)r*Dm + c) = ov;
    float h0 = __bfloat162float(__float2bfloat16(o0));
    float h1 = __bfloat162float(__float2bfloat16(o1));
    *reinterpret_cast<uint32_t*>(xh + (size_t)r*Dm + c) = pack2(o0, o1);
    *reinterpret_cast<uint32_t*>(xl + (size_t)r*Dm + c) = pack2(o0 - h0, o1 - h1);
}

extern "C" void kernel_launch(void* const* d_in, const int* in_sizes, int n_in,
                              void* d_out, int out_size)
{
    const float* x    = (const float*)d_in[0];
    const float* Wq   = (const float*)d_in[1];
    const float* bq   = (const float*)d_in[2];
    const float* Wk   = (const float*)d_in[3];
    const float* bk   = (const float*)d_in[4];
    const float* Wv   = (const float*)d_in[5];
    const float* bv   = (const float*)d_in[6];
    const float* Wo   = (const float*)d_in[7];
    const float* bo   = (const float*)d_in[8];
    const float* ln1g = (const float*)d_in[9];
    const float* ln1b = (const float*)d_in[10];
    const float* W1   = (const float*)d_in[11];
    const float* b1   = (const float*)d_in[12];
    const float* W2   = (const float*)d_in[13];
    const float* b2   = (const float*)d_in[14];
    const float* ln2g = (const float*)d_in[15];
    const float* ln2b = (const float*)d_in[16];
    const float* Wp   = (const float*)d_in[17];
    const float* bp   = (const float*)d_in[18];

    float *gx, *gt;
    cudaGetSymbolAddress((void**)&gx, g_x);
    cudaGetSymbolAddress((void**)&gt, g_tmp);
    __nv_bfloat16 *xh, *xl, *qh, *ql, *kh, *kl, *vh, *vl, *hh, *hl, *oh1, *ol1;
    cudaGetSymbolAddress((void**)&xh, g_xh); cudaGetSymbolAddress((void**)&xl, g_xl);
    cudaGetSymbolAddress((void**)&qh, g_qh); cudaGetSymbolAddress((void**)&ql, g_ql);
    cudaGetSymbolAddress((void**)&kh, g_kh); cudaGetSymbolAddress((void**)&kl, g_kl);
    cudaGetSymbolAddress((void**)&vh, g_vh); cudaGetSymbolAddress((void**)&vl, g_vl);
    cudaGetSymbolAddress((void**)&hh, g_hh); cudaGetSymbolAddress((void**)&hl, g_hl);
    cudaGetSymbolAddress((void**)&oh1, g_1h); cudaGetSymbolAddress((void**)&ol1, g_1l);
    __nv_bfloat16 *qkvh, *qkvl, *woh, *wol, *w1h, *w1l, *w2h, *w2l, *wph, *wpl;
    cudaGetSymbolAddress((void**)&qkvh, g_wqkv_h);
    cudaGetSymbolAddress((void**)&qkvl, g_wqkv_l);
    cudaGetSymbolAddress((void**)&woh, g_wo_h);
    cudaGetSymbolAddress((void**)&wol, g_wo_l);
    cudaGetSymbolAddress((void**)&w1h, g_w1_h);
    cudaGetSymbolAddress((void**)&w1l, g_w1_l);
    cudaGetSymbolAddress((void**)&w2h, g_w2_h);
    cudaGetSymbolAddress((void**)&w2l, g_w2_l);
    cudaGetSymbolAddress((void**)&wph, g_wp_h);
    cudaGetSymbolAddress((void**)&wpl, g_wp_l);

    const int gemm_smem  = 3 * GSTG;               // 221184
    const int flash_smem = 2*256*RSB + 3 * FSTG;   // 184320
    cudaFuncSetAttribute(gemm_mma, cudaFuncAttributeMaxDynamicSharedMemorySize, gemm_smem);
    cudaFuncSetAttribute(flash_mma, cudaFuncAttributeMaxDynamicSharedMemorySize, flash_smem);

    conv_x<<<Mrows*Dm/512, 256>>>(x, gx, xh, xl);
    prep_qkv_w<<<dim3(16, 2, 48), dim3(32, 8)>>>(Wq, Wk, Wv, qkvh, qkvl);
    prep_all<<<dim3(16, 16, 7), dim3(32, 8)>>>(Wo, W1, W2, Wp,
        woh, wol, w1h, w1l, w2h, w2l, wph, wpl);

    for (int l = 0; l < Ll; l++) {
        const __nv_bfloat16* qkvh_l = qkvh + (size_t)l * 1536 * 512;
        const __nv_bfloat16* qkvl_l = qkvl + (size_t)l * 1536 * 512;

        gemm_mma<<<dim3(12, 32), 512, gemm_smem>>>(xh, xl, qkvh_l, qkvl_l,
            bq + (size_t)l*512, bk + (size_t)l*512, bv + (size_t)l*512,
            0, qh, ql, kh, kl, vh, vl, 0, 0, 1);

        flash_mma<<<dim3(Slen/256, Hh, Bsz), 512, flash_smem>>>(
            qh, ql, kh, kl, vh, vl, hh, hl);

        gemm_mma<<<dim3(4, 32), 512, gemm_smem>>>(hh, hl,
            woh + (size_t)l*512*512, wol + (size_t)l*512*512,
            bo + (size_t)l*512, 0, 0, gt, 0, 0, 0, 0, 0, 0, 512, 0, 0);
        addln_kernel<<<Mrows, 256>>>(gx, gt, ln1g + (size_t)l*Dm, ln1b + (size_t)l*Dm, xh, xl);

        gemm_mma<<<dim3(4, 32), 512, gemm_smem>>>(xh, xl,
            w1h + (size_t)l*512*512, w1l + (size_t)l*512*512,
            b1 + (size_t)l*512, 0, 0, 0, oh1, ol1, 0, 0, 0, 0, 512, 1, 2);
        gemm_mma<<<dim3(4, 32), 512, gemm_smem>>>(oh1, ol1,
            w2h + (size_t)l*512*512, w2l + (size_t)l*512*512,
            b2 + (size_t)l*512, 0, 0, gt, 0, 0, 0, 0, 0, 0, 512, 0, 0);
        addln_kernel<<<Mrows, 256>>>(gx, gt, ln2g + (size_t)l*Dm, ln2b + (size_t)l*Dm, xh, xl);
    }

    gemm_mma<<<dim3(2, 32), 512, gemm_smem>>>(xh, xl, wph, wpl,
        bp, 0, 0, (float*)d_out, 0, 0, 0, 0, 0, 0, 256, 0, 0);
}

// round 16
// speedup vs baseline: 1.0041x; 1.0041x over previous
#include <cuda_runtime.h>
#include <cuda_bf16.h>
#include <math.h>
#include <stdint.h>

#define Bsz 2
#define Slen 2048
#define Dm 512
#define Hh 8
#define Aa 64
#define Ll 2
#define Tt 256
#define Mrows (Bsz*Slen)
#define LN_EPS 1e-5f

__device__ float g_x[Mrows*Dm];
__device__ float g_tmp[Mrows*Dm];
__device__ __nv_bfloat16 g_xh[Mrows*Dm],  g_xl[Mrows*Dm];
__device__ __nv_bfloat16 g_qh[Bsz*Hh*Slen*Aa], g_ql[Bsz*Hh*Slen*Aa];
__device__ __nv_bfloat16 g_kh[Bsz*Hh*Slen*Aa], g_kl[Bsz*Hh*Slen*Aa];
__device__ __nv_bfloat16 g_vh[Bsz*Hh*Slen*Aa], g_vl[Bsz*Hh*Slen*Aa];
__device__ __nv_bfloat16 g_hh[Mrows*Dm],  g_hl[Mrows*Dm];
__device__ __nv_bfloat16 g_1h[Mrows*Dm],  g_1l[Mrows*Dm];
__device__ __nv_bfloat16 g_wqkv_h[Ll*1536*512], g_wqkv_l[Ll*1536*512];
__device__ __nv_bfloat16 g_wo_h[Ll*512*512],    g_wo_l[Ll*512*512];
__device__ __nv_bfloat16 g_w1_h[Ll*512*512],    g_w1_l[Ll*512*512];
__device__ __nv_bfloat16 g_w2_h[Ll*512*512],    g_w2_l[Ll*512*512];
__device__ __nv_bfloat16 g_wp_h[Tt*512],        g_wp_l[Tt*512];

__device__ __forceinline__ uint32_t smem_u32(const void* p) {
    uint32_t a;
    asm("{ .reg .u64 t; cvta.to.shared.u64 t, %1; cvt.u32.u64 %0, t; }" : "=r"(a) : "l"(p));
    return a;
}
__device__ __forceinline__ uint32_t pack2(float x, float y) {
    return (uint32_t)__bfloat16_as_ushort(__float2bfloat16(x)) |
           ((uint32_t)__bfloat16_as_ushort(__float2bfloat16(y)) << 16);
}
__device__ __forceinline__ void ldsm4(uint32_t* r, uint32_t addr) {
    asm volatile("ldmatrix.sync.aligned.m8n8.x4.shared.b16 {%0,%1,%2,%3}, [%4];"
        : "=r"(r[0]), "=r"(r[1]), "=r"(r[2]), "=r"(r[3]) : "r"(addr));
}
__device__ __forceinline__ void ldsm4t(uint32_t* r, uint32_t addr) {
    asm volatile("ldmatrix.sync.aligned.m8n8.x4.trans.shared.b16 {%0,%1,%2,%3}, [%4];"
        : "=r"(r[0]), "=r"(r[1]), "=r"(r[2]), "=r"(r[3]) : "r"(addr));
}
__device__ __forceinline__ void mma16816(float* d, const uint32_t* a, const uint32_t* b) {
    asm volatile("mma.sync.aligned.m16n8k16.row.col.f32.bf16.bf16.f32 "
        "{%0,%1,%2,%3}, {%4,%5,%6,%7}, {%8,%9}, {%0,%1,%2,%3};"
        : "+f"(d[0]), "+f"(d[1]), "+f"(d[2]), "+f"(d[3])
        : "r"(a[0]), "r"(a[1]), "r"(a[2]), "r"(a[3]), "r"(b[0]), "r"(b[1]));
}
#define CP16(sa, gp) asm volatile("cp.async.cg.shared.global [%0], [%1], 16;" :: "r"(sa), "l"(gp))
#define CP_COMMIT()  asm volatile("cp.async.commit_group;" ::: "memory")
#define CP_WAIT0()   asm volatile("cp.async.wait_group 0;" ::: "memory")
#define CP_WAIT1()   asm volatile("cp.async.wait_group 1;" ::: "memory")

#define RSB 144
#define GSTG (4*128*RSB)    // 73728
#define FSTG (4*64*RSB)     // 36864

// ---- input convert ----
__global__ __launch_bounds__(256)
void conv_x(const float* __restrict__ xin, float* __restrict__ xout,
            __nv_bfloat16* __restrict__ xh, __nv_bfloat16* __restrict__ xl)
{
    int i = blockIdx.x * 256 + threadIdx.x;
    float2 v = *reinterpret_cast<const float2*>(xin + 2*i);
    *reinterpret_cast<float2*>(xout + 2*i) = v;
    float hx = __bfloat162float(__float2bfloat16(v.x));
    float hy = __bfloat162float(__float2bfloat16(v.y));
    *reinterpret_cast<uint32_t*>(xh + 2*i) = pack2(v.x, v.y);
    *reinterpret_cast<uint32_t*>(xl + 2*i) = pack2(v.x - hx, v.y - hy);
}

// ---- weight prep ----
__global__ void prep_all(const float* __restrict__ Wo, const float* __restrict__ W1,
                         const float* __restrict__ W2, const float* __restrict__ Wp,
                         __nv_bfloat16* __restrict__ woh, __nv_bfloat16* __restrict__ wol,
                         __nv_bfloat16* __restrict__ w1h, __nv_bfloat16* __restrict__ w1l,
                         __nv_bfloat16* __restrict__ w2h, __nv_bfloat16* __restrict__ w2l,
                         __nv_bfloat16* __restrict__ wph, __nv_bfloat16* __restrict__ wpl)
{
    int z = blockIdx.z;
    const float* W; __nv_bfloat16 *hi, *lo; int N;
    if (z < 2)      { W = Wo + (size_t)z*512*512; hi = woh + (size_t)z*512*512; lo = wol + (size_t)z*512*512; N = 512; }
    else if (z < 4) { int l = z-2; W = W1 + (size_t)l*512*512; hi = w1h + (size_t)l*512*512; lo = w1l + (size_t)l*512*512; N = 512; }
    else if (z < 6) { int l = z-4; W = W2 + (size_t)l*512*512; hi = w2h + (size_t)l*512*512; lo = w2l + (size_t)l*512*512; N = 512; }
    else            { W = Wp; hi = wph; lo = wpl; N = 256; }
    int k0 = blockIdx.x * 32, n0 = blockIdx.y * 32;
    if (n0 >= N) return;
    __shared__ float t[32][33];
    for (int i = threadIdx.y; i < 32; i += 8)
        t[i][threadIdx.x] = W[(size_t)(k0 + i) * N + n0 + threadIdx.x];
    __syncthreads();
    for (int i = threadIdx.y; i < 32; i += 8) {
        float v = t[threadIdx.x][i];
        __nv_bfloat16 h = __float2bfloat16(v);
        hi[(size_t)(n0 + i) * 512 + k0 + threadIdx.x] = h;
        lo[(size_t)(n0 + i) * 512 + k0 + threadIdx.x] = __float2bfloat16(v - __bfloat162float(h));
    }
}
__global__ void prep_qkv_w(const float* __restrict__ Wq, const float* __restrict__ Wk,
                           const float* __restrict__ Wv,
                           __nv_bfloat16* __restrict__ hi, __nv_bfloat16* __restrict__ lo)
{
    int bz = blockIdx.z;
    int l = bz / 24, rem = bz % 24, zz = rem / 8, h = rem % 8;
    const float* W = (zz == 0 ? Wq : zz == 1 ? Wk : Wv) + ((size_t)(l * Hh + h)) * Dm * Aa;
    size_t nb = (size_t)l * 1536 + zz * 512 + h * 64;
    __shared__ float t[32][33];
    int d0 = blockIdx.x * 32, a0 = blockIdx.y * 32;
    for (int i = threadIdx.y; i < 32; i += 8)
        t[i][threadIdx.x] = W[(size_t)(d0 + i) * Aa + a0 + threadIdx.x];
    __syncthreads();
    for (int i = threadIdx.y; i < 32; i += 8) {
        float v = t[threadIdx.x][i];
        __nv_bfloat16 hv = __float2bfloat16(v);
        hi[(nb + a0 + i) * 512 + d0 + threadIdx.x] = hv;
        lo[(nb + a0 + i) * 512 + d0 + threadIdx.x] = __float2bfloat16(v - __bfloat162float(hv));
    }
}

// ---------------------------------------------------------------------------
// HMMA GEMM (R8 tiles): 512 thr, CTA 128x128, 3 stages, prefetch-dist-2,
// ONE __syncthreads per chunk.
// ---------------------------------------------------------------------------
__global__ __launch_bounds__(512)
void gemm_mma(const __nv_bfloat16* __restrict__ Ah_g, const __nv_bfloat16* __restrict__ Al_g,
              const __nv_bfloat16* __restrict__ Bh_g, const __nv_bfloat16* __restrict__ Bl_g,
              const float* __restrict__ bias0, const float* __restrict__ bias1,
              const float* __restrict__ bias2,
              float* __restrict__ C0,
              __nv_bfloat16* __restrict__ H0, __nv_bfloat16* __restrict__ L0,
              __nv_bfloat16* __restrict__ H1, __nv_bfloat16* __restrict__ L1,
              __nv_bfloat16* __restrict__ H2, __nv_bfloat16* __restrict__ L2,
              int ldC, int relu, int mode)
{
    extern __shared__ char smem[];
    const uint32_t uS = smem_u32(smem);

    const int tid = threadIdx.x;
    const int wid = tid >> 5, lid = tid & 31;
    const int wm = wid >> 2, wn = wid & 3;
    const int g = lid >> 2, tg = lid & 3;
    const int m0 = blockIdx.y * 128, n0 = blockIdx.x * 128;

    float acc[2][4][4];
    #pragma unroll
    for (int i = 0; i < 2; i++)
        #pragma unroll
        for (int j = 0; j < 4; j++)
            #pragma unroll
            for (int e = 0; e < 4; e++) acc[i][j][e] = 0.0f;

    const int a_row = (lid & 7) + ((lid >> 3) & 1) * 8;
    const int a_colb = ((lid >> 4) & 1) * 16;
    const int b_row = (lid & 7) + ((lid >> 4) & 1) * 8;
    const int b_colb = ((lid >> 3) & 1) * 16;
    const int ld_row = tid >> 3, ld_kq = tid & 7;

    auto load_chunk = [&](int c, int st) {
        const uint32_t sb = uS + (uint32_t)st * GSTG;
        const int kt = c * 64;
        #pragma unroll
        for (int it = 0; it < 2; it++) {
            int row = ld_row + it * 64;
            const size_t ba = (size_t)(m0 + row) * 512 + kt + ld_kq * 8;
            uint32_t so = (uint32_t)(row * RSB + ld_kq * 16);
            CP16(sb + so,            Ah_g + ba);
            CP16(sb + 128*RSB + so,  Al_g + ba);
            const size_t bb = (size_t)(n0 + row) * 512 + kt + ld_kq * 8;
            CP16(sb + 2*128*RSB + so, Bh_g + bb);
            CP16(sb + 3*128*RSB + so, Bl_g + bb);
        }
    };

    load_chunk(0, 0); CP_COMMIT();
    load_chunk(1, 1); CP_COMMIT();

    for (int c = 0; c < 8; c++) {
        if (c == 7) CP_WAIT0(); else CP_WAIT1();
        __syncthreads();
        if (c + 2 < 8) { load_chunk(c + 2, (c + 2) % 3); CP_COMMIT(); }

        const uint32_t sb = uS + (uint32_t)(c % 3) * GSTG;
        const uint32_t uAh = sb, uAl = sb + 128*RSB;
        const uint32_t uBh = sb + 2*128*RSB, uBl = sb + 3*128*RSB;

        #pragma unroll
        for (int ks = 0; ks < 4; ks++) {
            const int kb = ks * 32;
            uint32_t bh[8], bl[8];
            #pragma unroll
            for (int jt = 0; jt < 2; jt++) {
                uint32_t addr = (wn * 32 + jt * 16 + b_row) * RSB + kb + b_colb;
                ldsm4(bh + jt * 4, uBh + addr);
                ldsm4(bl + jt * 4, uBl + addr);
            }
            #pragma unroll
            for (int i = 0; i < 2; i++) {
                uint32_t ah[4], al[4];
                uint32_t addr = (wm * 32 + i * 16 + a_row) * RSB + kb + a_colb;
                ldsm4(ah, uAh + addr);
                ldsm4(al, uAl + addr);
                #pragma unroll
                for (int j = 0; j < 4; j++) {
                    mma16816(acc[i][j], ah, bh + j * 2);
                    mma16816(acc[i][j], ah, bl + j * 2);
                    mma16816(acc[i][j], al, bh + j * 2);
                }
            }
        }
    }

    const int mb = m0 + wm * 32;
    const int nb = n0 + wn * 32;
    #pragma unroll
    for (int i = 0; i < 2; i++) {
        #pragma unroll
        for (int rhalf = 0; rhalf < 2; rhalf++) {
            const int m = mb + i * 16 + g + rhalf * 8;
            const int b_ = m >> 11, s = m & 2047;
            #pragma unroll
            for (int j = 0; j < 4; j++) {
                const int ncol = nb + j * 8 + 2 * tg;
                float vx = acc[i][j][rhalf * 2 + 0];
                float vy = acc[i][j][rhalf * 2 + 1];
                if (mode == 0) {
                    vx += bias0[ncol]; vy += bias0[ncol + 1];
                    if (relu) { vx = fmaxf(vx, 0.f); vy = fmaxf(vy, 0.f); }
                    float2 o = {vx, vy};
                    *reinterpret_cast<float2*>(C0 + (size_t)m * ldC + ncol) = o;
                } else if (mode == 1) {
                    const int z = ncol >> 9, rr = ncol & 511;
                    const int h = rr >> 6, a = rr & 63;
                    const float* bias = (z == 0) ? bias0 : (z == 1) ? bias1 : bias2;
                    vx += bias[rr]; vy += bias[rr + 1];
                    if (z == 0) { vx *= 0.125f; vy *= 0.125f; }
                    __nv_bfloat16* Hp = (z == 0) ? H0 : (z == 1) ? H1 : H2;
                    __nv_bfloat16* Lp = (z == 0) ? L0 : (z == 1) ? L1 : L2;
                    const size_t off = (((size_t)(b_ * Hh + h) * Slen + s) * 64) + a;
                    float hx = __bfloat162float(__float2bfloat16(vx));
                    float hy = __bfloat162float(__float2bfloat16(vy));
                    *reinterpret_cast<uint32_t*>(Hp + off) = pack2(vx, vy);
                    *reinterpret_cast<uint32_t*>(Lp + off) = pack2(vx - hx, vy - hy);
                } else {
                    vx += bias0[ncol]; vy += bias0[ncol + 1];
                    vx = fmaxf(vx, 0.f); vy = fmaxf(vy, 0.f);
                    const size_t off = (size_t)m * ldC + ncol;
                    float hx = __bfloat162float(__float2bfloat16(vx));
                    float hy = __bfloat162float(__float2bfloat16(vy));
                    *reinterpret_cast<uint32_t*>(H0 + off) = pack2(vx, vy);
                    *reinterpret_cast<uint32_t*>(L0 + off) = pack2(vx - hx, vy - hy);
                }
            }
        }
    }
}

// ---------------------------------------------------------------------------
// Flash attention (R8 tiles): 512 thr, 256 q/CTA, 3-stage KV, prefetch-dist-2,
// ONE __syncthreads per chunk. smem = 73728 + 3*36864 = 184320.
// ---------------------------------------------------------------------------
__global__ __launch_bounds__(512)
void flash_mma(const __nv_bfloat16* __restrict__ Qh, const __nv_bfloat16* __restrict__ Ql,
               const __nv_bfloat16* __restrict__ Kh, const __nv_bfloat16* __restrict__ Kl,
               const __nv_bfloat16* __restrict__ Vh, const __nv_bfloat16* __restrict__ Vl,
               __nv_bfloat16* __restrict__ Oh, __nv_bfloat16* __restrict__ Ol)
{
    extern __shared__ char smem[];
    const uint32_t uQh = smem_u32(smem);
    const uint32_t uQl = uQh + 256*RSB;
    const uint32_t uKV = uQh + 2*256*RSB;

    const int s0 = blockIdx.x * 256, h = blockIdx.y, b = blockIdx.z;
    const size_t bh_off = ((size_t)(b*Hh + h) * Slen) * Aa;
    const __nv_bfloat16* Qhb = Qh + bh_off; const __nv_bfloat16* Qlb = Ql + bh_off;
    const __nv_bfloat16* Khb = Kh + bh_off; const __nv_bfloat16* Klb = Kl + bh_off;
    const __nv_bfloat16* Vhb = Vh + bh_off; const __nv_bfloat16* Vlb = Vl + bh_off;

    const int tid = threadIdx.x;
    const int wid = tid >> 5, lid = tid & 31;
    const int ld_row = tid >> 3, ld_kq = tid & 7;

    // Q tile (joins cp.async group 0)
    #pragma unroll
    for (int it = 0; it < 4; it++) {
        int row = ld_row + it * 64;
        const size_t base = (size_t)(s0 + row) * Aa + ld_kq * 8;
        uint32_t so = (uint32_t)(row * RSB + ld_kq * 16);
        CP16(uQh + so, Qhb + base);
        CP16(uQl + so, Qlb + base);
    }

    auto loadKV = [&](int ci, int st) {
        const uint32_t sb = uKV + (uint32_t)st * FSTG;
        const int c0 = ci * 64;
        const size_t base = (size_t)(c0 + ld_row) * Aa + ld_kq * 8;
        uint32_t so = (uint32_t)(ld_row * RSB + ld_kq * 16);
        CP16(sb + so,            Khb + base);
        CP16(sb + 64*RSB + so,   Klb + base);
        CP16(sb + 2*64*RSB + so, Vhb + base);
        CP16(sb + 3*64*RSB + so, Vlb + base);
    };

    loadKV(0, 0); CP_COMMIT();
    loadKV(1, 1); CP_COMMIT();

    const int a_row = (lid & 7) + ((lid >> 3) & 1) * 8;
    const int a_colb = ((lid >> 4) & 1) * 16;
    const int b_row = (lid & 7) + ((lid >> 4) & 1) * 8;
    const int b_colb = ((lid >> 3) & 1) * 16;
    const int v_row = (lid & 7) + ((lid >> 3) & 1) * 8;
    const int v_colb = ((lid >> 4) & 1) * 16;

    float m0 = -INFINITY, m1 = -INFINITY, l0 = 0.0f, l1 = 0.0f;
    float accO[8][4];
    #pragma unroll
    for (int j = 0; j < 8; j++)
        #pragma unroll
        for (int e = 0; e < 4; e++) accO[j][e] = 0.0f;

    const int NC = Slen / 64;
    for (int ci = 0; ci < NC; ci++) {
        if (ci == NC - 1) CP_WAIT0(); else CP_WAIT1();
        __syncthreads();
        if (ci + 2 < NC) { loadKV(ci + 2, (ci + 2) % 3); CP_COMMIT(); }

        const uint32_t sb = uKV + (uint32_t)(ci % 3) * FSTG;
        const uint32_t uKh = sb, uKl = sb + 64*RSB;
        const uint32_t uVh = sb + 2*64*RSB, uVl = sb + 3*64*RSB;

        float accS[8][4];
        #pragma unroll
        for (int j = 0; j < 8; j++)
            #pragma unroll
            for (int e = 0; e < 4; e++) accS[j][e] = 0.0f;

        #pragma unroll
        for (int ks = 0; ks < 4; ks++) {
            const int kb = ks * 32;
            uint32_t qh[4], ql[4];
            ldsm4(qh, uQh + (wid * 16 + a_row) * RSB + kb + a_colb);
            ldsm4(ql, uQl + (wid * 16 + a_row) * RSB + kb + a_colb);
            uint32_t kh[16], kl[16];
            #pragma unroll
            for (int jt = 0; jt < 4; jt++) {
                uint32_t addr = (jt * 16 + b_row) * RSB + kb + b_colb;
                ldsm4(kh + jt * 4, uKh + addr);
                ldsm4(kl + jt * 4, uKl + addr);
            }
            #pragma unroll
            for (int j = 0; j < 8; j++) {
                const int base = (j >> 1) * 4 + (j & 1) * 2;
                mma16816(accS[j], qh, kh + base);
                mma16816(accS[j], qh, kl + base);
                mma16816(accS[j], ql, kh + base);
            }
        }

        float mx0 = -INFINITY, mx1 = -INFINITY;
        #pragma unroll
        for (int j = 0; j < 8; j++) {
            mx0 = fmaxf(mx0, fmaxf(accS[j][0], accS[j][1]));
            mx1 = fmaxf(mx1, fmaxf(accS[j][2], accS[j][3]));
        }
        mx0 = fmaxf(mx0, __shfl_xor_sync(0xffffffffu, mx0, 1));
        mx0 = fmaxf(mx0, __shfl_xor_sync(0xffffffffu, mx0, 2));
        mx1 = fmaxf(mx1, __shfl_xor_sync(0xffffffffu, mx1, 1));
        mx1 = fmaxf(mx1, __shfl_xor_sync(0xffffffffu, mx1, 2));
        const float mn0 = fmaxf(m0, mx0), mn1 = fmaxf(m1, mx1);
        const float fac0 = __expf(m0 - mn0), fac1 = __expf(m1 - mn1);
        float sum0 = 0.0f, sum1 = 0.0f;
        #pragma unroll
        for (int j = 0; j < 8; j++) {
            accS[j][0] = __expf(accS[j][0] - mn0);
            accS[j][1] = __expf(accS[j][1] - mn0);
            accS[j][2] = __expf(accS[j][2] - mn1);
            accS[j][3] = __expf(accS[j][3] - mn1);
            sum0 += accS[j][0] + accS[j][1];
            sum1 += accS[j][2] + accS[j][3];
        }
        sum0 += __shfl_xor_sync(0xffffffffu, sum0, 1);
        sum0 += __shfl_xor_sync(0xffffffffu, sum0, 2);
        sum1 += __shfl_xor_sync(0xffffffffu, sum1, 1);
        sum1 += __shfl_xor_sync(0xffffffffu, sum1, 2);
        l0 = l0 * fac0 + sum0;  m0 = mn0;
        l1 = l1 * fac1 + sum1;  m1 = mn1;
        #pragma unroll
        for (int j = 0; j < 8; j++) {
            accO[j][0] *= fac0; accO[j][1] *= fac0;
            accO[j][2] *= fac1; accO[j][3] *= fac1;
        }

        #pragma unroll
        for (int ks = 0; ks < 4; ks++) {
            uint32_t ph[4], pl[4];
            {
                const float* p0 = accS[2*ks];
                const float* p1 = accS[2*ks + 1];
                float h00 = __bfloat162float(__float2bfloat16(p0[0]));
                float h01 = __bfloat162float(__float2bfloat16(p0[1]));
                float h02 = __bfloat162float(__float2bfloat16(p0[2]));
                float h03 = __bfloat162float(__float2bfloat16(p0[3]));
                float h10 = __bfloat162float(__float2bfloat16(p1[0]));
                float h11 = __bfloat162float(__float2bfloat16(p1[1]));
                float h12 = __bfloat162float(__float2bfloat16(p1[2]));
                float h13 = __bfloat162float(__float2bfloat16(p1[3]));
                ph[0] = pack2(p0[0], p0[1]);  ph[1] = pack2(p0[2], p0[3]);
                ph[2] = pack2(p1[0], p1[1]);  ph[3] = pack2(p1[2], p1[3]);
                pl[0] = pack2(p0[0]-h00, p0[1]-h01);
                pl[1] = pack2(p0[2]-h02, p0[3]-h03);
                pl[2] = pack2(p1[0]-h10, p1[1]-h11);
                pl[3] = pack2(p1[2]-h12, p1[3]-h13);
            }
            uint32_t vh[16], vl[16];
            #pragma unroll
            for (int jt = 0; jt < 4; jt++) {
                uint32_t addr = (ks * 16 + v_row) * RSB + jt * 32 + v_colb;
                ldsm4t(vh + jt * 4, uVh + addr);
                ldsm4t(vl + jt * 4, uVl + addr);
            }
            #pragma unroll
            for (int j = 0; j < 8; j++) {
                const int base = (j >> 1) * 4 + (j & 1) * 2;
                mma16816(accO[j], ph, vh + base);
                mma16816(accO[j], ph, vl + base);
                mma16816(accO[j], pl, vh + base);
            }
        }
    }

    const float inv0 = 1.0f / l0, inv1 = 1.0f / l1;
    const int r0 = s0 + wid * 16 + (lid >> 2);
    const int r1 = r0 + 8;
    #pragma unroll
    for (int j = 0; j < 8; j++) {
        const int a = j * 8 + 2 * (lid & 3);
        float x0 = accO[j][0] * inv0, y0 = accO[j][1] * inv0;
        float x1 = accO[j][2] * inv1, y1 = accO[j][3] * inv1;
        float hx0 = __bfloat162float(__float2bfloat16(x0));
        float hy0 = __bfloat162float(__float2bfloat16(y0));
        float hx1 = __bfloat162float(__float2bfloat16(x1));
        float hy1 = __bfloat162float(__float2bfloat16(y1));
        const size_t o0 = (((size_t)b * Slen + r0) * Hh + h) * Aa + a;
        const size_t o1 = (((size_t)b * Slen + r1) * Hh + h) * Aa + a;
        *reinterpret_cast<uint32_t*>(Oh + o0) = pack2(x0, y0);
        *reinterpret_cast<uint32_t*>(Ol + o0) = pack2(x0 - hx0, y0 - hy0);
        *reinterpret_cast<uint32_t*>(Oh + o1) = pack2(x1, y1);
        *reinterpret_cast<uint32_t*>(Ol + o1) = pack2(x1 - hx1, y1 - hy1);
    }
}

// ---------------- fused add + LayerNorm ----------------
__global__ __launch_bounds__(256)
void addln_kernel(float* __restrict__ x, const float* __restrict__ t,
                  const float* __restrict__ g, const float* __restrict__ beta,
                  __nv_bfloat16* __restrict__ xh, __nv_bfloat16* __restrict__ xl)
{
    const int r = blockIdx.x, tid = threadIdx.x;
    const int c = 2 * tid;
    float2 xv = *reinterpret_cast<const float2*>(x + (size_t)r*Dm + c);
    float2 tv = *reinterpret_cast<const float2*>(t + (size_t)r*Dm + c);
    float v0 = xv.x + tv.x, v1 = xv.y + tv.y;
    float s = v0 + v1, ss = v0*v0 + v1*v1;
    #pragma unroll
    for (int off = 16; off >= 1; off >>= 1) {
        s  += __shfl_xor_sync(0xffffffffu, s,  off);
        ss += __shfl_xor_sync(0xffffffffu, ss, off);
    }
    __shared__ float red_s[8], red_ss[8], sm_mean, sm_rstd;
    int wid = tid >> 5, lane = tid & 31;
    if (lane == 0) { red_s[wid] = s; red_ss[wid] = ss; }
    __syncthreads();
    if (tid == 0) {
        float S = 0.f, SS = 0.f;
        #pragma unroll
        for (int w = 0; w < 8; w++) { S += red_s[w]; SS += red_ss[w]; }
        float mean = S * (1.0f / Dm);
        sm_mean = mean;
        sm_rstd = rsqrtf(SS * (1.0f / Dm) - mean * mean + LN_EPS);
    }
    __syncthreads();
    float mean = sm_mean, rstd = sm_rstd;
    float2 gv = *reinterpret_cast<const float2*>(g + c);
    float2 bv = *reinterpret_cast<const float2*>(beta + c);
    float o0 = (v0 - mean) * rstd * gv.x + bv.x;
    float o1 = (v1 - mean) * rstd * gv.y + bv.y;
    float2 ov = {o0, o1};
    *reinterpret_cast<float2*>(x + (size_t)r*Dm + c) = ov;
    float h0 = __bfloat162float(__float2bfloat16(o0));
    float h1 = __bfloat162float(__float2bfloat16(o1));
    *reinterpret_cast<uint32_t*>(xh + (size_t)r*Dm + c) = pack2(o0, o1);
    *reinterpret_cast<uint32_t*>(xl + (size_t)r*Dm + c) = pack2(o0 - h0, o1 - h1);
}

extern "C" void kernel_launch(void* const* d_in, const int* in_sizes, int n_in,
                              void* d_out, int out_size)
{
    const float* x    = (const float*)d_in[0];
    const float* Wq   = (const float*)d_in[1];
    const float* bq   = (const float*)d_in[2];
    const float* Wk   = (const float*)d_in[3];
    const float* bk   = (const float*)d_in[4];
    const float* Wv   = (const float*)d_in[5];
    const float* bv   = (const float*)d_in[6];
    const float* Wo   = (const float*)d_in[7];
    const float* bo   = (const float*)d_in[8];
    const float* ln1g = (const float*)d_in[9];
    const float* ln1b = (const float*)d_in[10];
    const float* W1   = (const float*)d_in[11];
    const float* b1   = (const float*)d_in[12];
    const float* W2   = (const float*)d_in[13];
    const float* b2   = (const float*)d_in[14];
    const float* ln2g = (const float*)d_in[15];
    const float* ln2b = (const float*)d_in[16];
    const float* Wp   = (const float*)d_in[17];
    const float* bp   = (const float*)d_in[18];

    float *gx, *gt;
    cudaGetSymbolAddress((void**)&gx, g_x);
    cudaGetSymbolAddress((void**)&gt, g_tmp);
    __nv_bfloat16 *xh, *xl, *qh, *ql, *kh, *kl, *vh, *vl, *hh, *hl, *oh1, *ol1;
    cudaGetSymbolAddress((void**)&xh, g_xh); cudaGetSymbolAddress((void**)&xl, g_xl);
    cudaGetSymbolAddress((void**)&qh, g_qh); cudaGetSymbolAddress((void**)&ql, g_ql);
    cudaGetSymbolAddress((void**)&kh, g_kh); cudaGetSymbolAddress((void**)&kl, g_kl);
    cudaGetSymbolAddress((void**)&vh, g_vh); cudaGetSymbolAddress((void**)&vl, g_vl);
    cudaGetSymbolAddress((void**)&hh, g_hh); cudaGetSymbolAddress((void**)&hl, g_hl);
    cudaGetSymbolAddress((void**)&oh1, g_1h); cudaGetSymbolAddress((void**)&ol1, g_1l);
    __nv_bfloat16 *qkvh, *qkvl, *woh, *wol, *w1h, *w1l, *w2h, *w2l, *wph, *wpl;
    cudaGetSymbolAddress((void**)&qkvh, g_wqkv_h);
    cudaGetSymbolAddress((void**)&qkvl, g_wqkv_l);
    cudaGetSymbolAddress((void**)&woh, g_wo_h);
    cudaGetSymbolAddress((void**)&wol, g_wo_l);
    cudaGetSymbolAddress((void**)&w1h, g_w1_h);
    cudaGetSymbolAddress((void**)&w1l, g_w1_l);
    cudaGetSymbolAddress((void**)&w2h, g_w2_h);
    cudaGetSymbolAddress((void**)&w2l, g_w2_l);
    cudaGetSymbolAddress((void**)&wph, g_wp_h);
    cudaGetSymbolAddress((void**)&wpl, g_wp_l);

    const int gemm_smem  = 3 * GSTG;               // 221184
    const int flash_smem = 2*256*RSB + 3 * FSTG;   // 184320
    cudaFuncSetAttribute(gemm_mma, cudaFuncAttributeMaxDynamicSharedMemorySize, gemm_smem);
    cudaFuncSetAttribute(flash_mma, cudaFuncAttributeMaxDynamicSharedMemorySize, flash_smem);

    conv_x<<<Mrows*Dm/512, 256>>>(x, gx, xh, xl);
    prep_qkv_w<<<dim3(16, 2, 48), dim3(32, 8)>>>(Wq, Wk, Wv, qkvh, qkvl);
    prep_all<<<dim3(16, 16, 7), dim3(32, 8)>>>(Wo, W1, W2, Wp,
        woh, wol, w1h, w1l, w2h, w2l, wph, wpl);

    for (int l = 0; l < Ll; l++) {
        const __nv_bfloat16* qkvh_l = qkvh + (size_t)l * 1536 * 512;
        const __nv_bfloat16* qkvl_l = qkvl + (size_t)l * 1536 * 512;

        gemm_mma<<<dim3(12, 32), 512, gemm_smem>>>(xh, xl, qkvh_l, qkvl_l,
            bq + (size_t)l*512, bk + (size_t)l*512, bv + (size_t)l*512,
            0, qh, ql, kh, kl, vh, vl, 0, 0, 1);

        flash_mma<<<dim3(Slen/256, Hh, Bsz), 512, flash_smem>>>(
            qh, ql, kh, kl, vh, vl, hh, hl);

        gemm_mma<<<dim3(4, 32), 512, gemm_smem>>>(hh, hl,
            woh + (size_t)l*512*512, wol + (size_t)l*512*512,
            bo + (size_t)l*512, 0, 0, gt, 0, 0, 0, 0, 0, 0, 512, 0, 0);
        addln_kernel<<<Mrows, 256>>>(gx, gt, ln1g + (size_t)l*Dm, ln1b + (size_t)l*Dm, xh, xl);

        gemm_mma<<<dim3(4, 32), 512, gemm_smem>>>(xh, xl,
            w1h + (size_t)l*512*512, w1l + (size_t)l*512*512,
            b1 + (size_t)l*512, 0, 0, 0, oh1, ol1, 0, 0, 0, 0, 512, 1, 2);
        gemm_mma<<<dim3(4, 32), 512, gemm_smem>>>(oh1, ol1,
            w2h + (size_t)l*512*512, w2l + (size_t)l*512*512,
            b2 + (size_t)l*512, 0, 0, gt, 0, 0, 0, 0, 0, 0, 512, 0, 0);
        addln_kernel<<<Mrows, 256>>>(gx, gt, ln2g + (size_t)l*Dm, ln2b + (size_t)l*Dm, xh, xl);
    }

    gemm_mma<<<dim3(2, 32), 512, gemm_smem>>>(xh, xl, wph, wpl,
        bp, 0, 0, (float*)d_out, 0, 0, 0, 0, 0, 0, 256, 0, 0);
}